// round 15
// baseline (speedup 1.0000x reference)
#include <cuda_runtime.h>
#include <cuda_bf16.h>
#include <cuda_fp16.h>
#include <cstdint>

#define N_NODES 16384
#define DIM 512
#define CAP2 128              // per-scanner-warp list capacity (mean 16.4, 27 sigma)
#define SPMM_GRID 888         // 148 SMs x 6 CTAs -> single persistent wave

// Scratch: single fp16 Y used for BOTH neighbor gathers and the self term.
__device__ __half g_Yh [(size_t)N_NODES * DIM];
__device__ __half g_xh [(size_t)N_NODES * DIM];   // fp16 x
__device__ __half g_Wh [(size_t)DIM * DIM];       // fp16 W^T [n][k]

__device__ __forceinline__ float2 h2f(uint32_t r) {
    return __half22float2(*(__half2*)&r);
}
__device__ __forceinline__ uint32_t smem_u32(const void* p) {
    uint32_t a;
    asm("{ .reg .u64 t; cvta.to.shared.u64 t, %1; cvt.u32.u64 %0, t; }" : "=r"(a) : "l"(p));
    return a;
}

#define CP_ASYNC16(saddr, gptr) \
    asm volatile("cp.async.cg.shared.global [%0], [%1], 16;" :: "r"(saddr), "l"(gptr) : "memory")
#define CP_COMMIT() asm volatile("cp.async.commit_group;" ::: "memory")
#define CP_WAIT2()  asm volatile("cp.async.wait_group 2;" ::: "memory")

#define LDMX4(r0, r1, r2, r3, addr) \
    asm volatile("ldmatrix.sync.aligned.m8n8.x4.shared.b16 {%0,%1,%2,%3}, [%4];" \
                 : "=r"(r0), "=r"(r1), "=r"(r2), "=r"(r3) : "r"(addr))

// ---------------------------------------------------------------------------
// Kernel 0: merged prepass (R14, unchanged).
// ---------------------------------------------------------------------------
__global__ void __launch_bounds__(256) prep_kernel(const float* __restrict__ x,
                                                   const float* __restrict__ W) {
    if (blockIdx.x < 8192) {
        const size_t i = ((size_t)blockIdx.x * 256 + threadIdx.x) * 4;
        float4 v = *(const float4*)(x + i);
        __half2 h0 = __floats2half2_rn(v.x, v.y);
        __half2 h1 = __floats2half2_rn(v.z, v.w);
        uint2 pk;
        pk.x = *(uint32_t*)&h0;
        pk.y = *(uint32_t*)&h1;
        *(uint2*)(g_xh + i) = pk;
    } else {
        __shared__ float t[32][33];
        const int b  = blockIdx.x - 8192;
        const int bx = (b & 15) * 32;
        const int by = (b >> 4) * 32;
        const int tx = threadIdx.x & 31;
        const int ty = threadIdx.x >> 5;
#pragma unroll
        for (int i = ty; i < 32; i += 8)
            t[i][tx] = W[(size_t)(by + i) * DIM + bx + tx];
        __syncthreads();
#pragma unroll
        for (int i = ty; i < 32; i += 8)
            g_Wh[(size_t)(bx + i) * DIM + by + tx] = __float2half_rn(t[tx][i]);
    }
}

// ---------------------------------------------------------------------------
// Kernel 1: Y = x @ W  (fp16 mma.sync m16n8k16 + ldmatrix + 3-stage cp.async)
// R14, unchanged.
// ---------------------------------------------------------------------------
#define STAGE_BYTES 32768
#define GEMM_SMEM   98304

__global__ void __launch_bounds__(256, 2) gemm_xw() {
    extern __shared__ char sm[];
    const uint32_t smb = smem_u32(sm);

    const int tid  = threadIdx.x;
    const int wid  = tid >> 5;
    const int lane = tid & 31;
    const int wm   = wid & 3;
    const int wn   = wid >> 2;

    const int m0 = blockIdx.y * 128;
    const int n0 = blockIdx.x * 128;

    #define PREF(t, s) do {                                                          \
        const int _kt = (t) * 64;                                                    \
        const uint32_t _ab = smb + (uint32_t)(s) * STAGE_BYTES;                      \
        const uint32_t _bb = _ab + 16384;                                            \
        _Pragma("unroll")                                                            \
        for (int _h = 0; _h < 4; _h++) {                                             \
            int _u = tid + _h * 256;                                                 \
            int _r = _u >> 3, _c = _u & 7;                                           \
            uint32_t _idx = (uint32_t)(_r * 8 + (_c ^ (_r & 7)));                    \
            CP_ASYNC16(_ab + _idx * 16, g_xh + (size_t)(m0 + _r) * DIM + _kt + _c * 8); \
            CP_ASYNC16(_bb + _idx * 16, g_Wh + (size_t)(n0 + _r) * DIM + _kt + _c * 8); \
        }                                                                            \
    } while (0)

    float c[2][8][4];
#pragma unroll
    for (int i = 0; i < 2; i++)
#pragma unroll
        for (int j = 0; j < 8; j++)
#pragma unroll
            for (int k = 0; k < 4; k++) c[i][j][k] = 0.f;

    PREF(0, 0); CP_COMMIT();
    PREF(1, 1); CP_COMMIT();
    PREF(2, 2); CP_COMMIT();

    const int a_row14 = lane & 15;
    const int a_chalf = lane >> 4;
    const int b_nrow  = (lane & 7) + ((lane >> 4) << 3);
    const int b_chalf = (lane >> 3) & 1;

#pragma unroll 1
    for (int t = 0; t < 8; t++) {
        CP_WAIT2();
        __syncthreads();
        const int s = t - (t / 3) * 3;
        const uint32_t Ab = smb + (uint32_t)s * STAGE_BYTES;
        const uint32_t Bb = Ab + 16384;

#pragma unroll
        for (int ks = 0; ks < 4; ks++) {
            uint32_t a[2][4], b[8][2];
#pragma unroll
            for (int mi = 0; mi < 2; mi++) {
                int row = wm * 32 + mi * 16 + a_row14;
                int cc  = ks * 2 + a_chalf;
                uint32_t addr = Ab + (uint32_t)(row * 8 + (cc ^ (row & 7))) * 16;
                LDMX4(a[mi][0], a[mi][1], a[mi][2], a[mi][3], addr);
            }
#pragma unroll
            for (int p = 0; p < 4; p++) {
                int n  = wn * 64 + p * 16 + b_nrow;
                int cc = ks * 2 + b_chalf;
                uint32_t addr = Bb + (uint32_t)(n * 8 + (cc ^ (n & 7))) * 16;
                LDMX4(b[2 * p][0], b[2 * p][1], b[2 * p + 1][0], b[2 * p + 1][1], addr);
            }
#pragma unroll
            for (int mi = 0; mi < 2; mi++)
#pragma unroll
                for (int ni = 0; ni < 8; ni++) {
                    asm volatile(
                        "mma.sync.aligned.m16n8k16.row.col.f32.f16.f16.f32 "
                        "{%0,%1,%2,%3}, {%4,%5,%6,%7}, {%8,%9}, {%0,%1,%2,%3};"
                        : "+f"(c[mi][ni][0]), "+f"(c[mi][ni][1]),
                          "+f"(c[mi][ni][2]), "+f"(c[mi][ni][3])
                        : "r"(a[mi][0]), "r"(a[mi][1]), "r"(a[mi][2]), "r"(a[mi][3]),
                          "r"(b[ni][0]), "r"(b[ni][1]));
                }
        }
        __syncthreads();
        if (t + 3 < 8) PREF(t + 3, s);
        CP_COMMIT();
    }

    const int g  = lane >> 2;
    const int tg = lane & 3;
#pragma unroll
    for (int mi = 0; mi < 2; mi++) {
#pragma unroll
        for (int ni = 0; ni < 8; ni++) {
            int row0 = m0 + wm * 32 + mi * 16 + g;
            int col  = n0 + wn * 64 + ni * 8 + tg * 2;
            __half2 h01 = __floats2half2_rn(c[mi][ni][0], c[mi][ni][1]);
            __half2 h23 = __floats2half2_rn(c[mi][ni][2], c[mi][ni][3]);
            *(__half2*)(g_Yh + (size_t)row0 * DIM + col)       = h01;
            *(__half2*)(g_Yh + (size_t)(row0 + 8) * DIM + col) = h23;
        }
    }
}

// ---------------------------------------------------------------------------
// Kernel 2: warp-specialized streamed aggregation.
// Persistent CTAs (grid 888 = 1 wave at 6 CTAs/SM), rows strided by gridDim.
// Warps 0-3 scan (4096 cols each, ldcs from global, ballot-compaction into
// double-buffered smem lists). Warps 4-7 gather the PREVIOUS row's edges
// (balanced stride-4), reduce among themselves (bar.sync 1), epilogue with
// streaming stores. One __syncthreads per row slot.
// ---------------------------------------------------------------------------
__global__ void __launch_bounds__(256, 6) gcn_spmm(const float* __restrict__ A,
                                                   const float* __restrict__ deg,
                                                   const float* __restrict__ bias,
                                                   float* __restrict__ out) {
    __shared__ uint16_t s_idx[2][4 * CAP2];
    __shared__ int      s_cnt[2][4];
    __shared__ float    s_part[4 * DIM];

    const int tid  = threadIdx.x;
    const int w    = tid >> 5;
    const int lane = tid & 31;
    const unsigned lml = (1u << lane) - 1u;
    const bool scanner = (w < 4);

    const int myrows = (N_NODES - blockIdx.x + SPMM_GRID - 1) / SPMM_GRID;

#pragma unroll 1
    for (int slot = 0; slot <= myrows; slot++) {
        if (scanner) {
            if (slot < myrows) {
                const int row = blockIdx.x + slot * SPMM_GRID;
                const int par = slot & 1;
                uint16_t* lst = s_idx[par] + w * CAP2;
                const uint4* Ar = (const uint4*)(A + (size_t)row * N_NODES + w * 4096);
                int cnt = 0;
#pragma unroll 1
                for (int bb = 0; bb < 4; bb++) {
                    uint4 v[8];
#pragma unroll
                    for (int k = 0; k < 8; k++)
                        v[k] = __ldcs(Ar + (bb * 8 + k) * 32 + lane);
#pragma unroll
                    for (int k = 0; k < 8; k++) {
                        unsigned nz = v[k].x | v[k].y | v[k].z | v[k].w;
                        if (__ballot_sync(0xFFFFFFFFu, nz != 0)) {
                            int colbase = w * 4096 + ((bb * 8 + k) * 32 + lane) * 4;
                            unsigned m;
                            m = __ballot_sync(0xFFFFFFFFu, v[k].x != 0);
                            if (v[k].x) { int p = cnt + __popc(m & lml); if (p < CAP2) lst[p] = (uint16_t)(colbase + 0); }
                            cnt += __popc(m);
                            m = __ballot_sync(0xFFFFFFFFu, v[k].y != 0);
                            if (v[k].y) { int p = cnt + __popc(m & lml); if (p < CAP2) lst[p] = (uint16_t)(colbase + 1); }
                            cnt += __popc(m);
                            m = __ballot_sync(0xFFFFFFFFu, v[k].z != 0);
                            if (v[k].z) { int p = cnt + __popc(m & lml); if (p < CAP2) lst[p] = (uint16_t)(colbase + 2); }
                            cnt += __popc(m);
                            m = __ballot_sync(0xFFFFFFFFu, v[k].w != 0);
                            if (v[k].w) { int p = cnt + __popc(m & lml); if (p < CAP2) lst[p] = (uint16_t)(colbase + 3); }
                            cnt += __popc(m);
                        }
                    }
                }
                if (lane == 0) s_cnt[par][w] = (cnt < CAP2) ? cnt : CAP2;
            }
        } else if (slot >= 1) {
            const int row = blockIdx.x + (slot - 1) * SPMM_GRID;
            const int par = (slot - 1) & 1;
            const int gw  = w - 4;
            const uint16_t* lp = s_idx[par];
            const int c0 = s_cnt[par][0];
            const int b2 = c0 + s_cnt[par][1];
            const int b3 = b2 + s_cnt[par][2];
            const int tot = b3 + s_cnt[par][3];

            float acc[16];
#pragma unroll
            for (int i = 0; i < 16; i++) acc[i] = 0.f;

            if (gw < tot) {
                #define IDX_OF(gg) ((gg) < c0 ? lp[(gg)] : (gg) < b2 ? lp[CAP2 + (gg) - c0] \
                                    : (gg) < b3 ? lp[2 * CAP2 + (gg) - b2] : lp[3 * CAP2 + (gg) - b3])
                int g = gw;
                int j = IDX_OF(g);
                const uint4* yp = (const uint4*)(g_Yh + (size_t)j * DIM);
                uint4 va = yp[lane];
                uint4 vb = yp[32 + lane];
#pragma unroll 1
                for (; g < tot; g += 4) {
                    int gn = (g + 4 < tot) ? (g + 4) : g;
                    int jn = IDX_OF(gn);
                    const uint4* ypn = (const uint4*)(g_Yh + (size_t)jn * DIM);
                    uint4 na = ypn[lane];
                    uint4 nb = ypn[32 + lane];

                    float2 f;
                    f = h2f(va.x); acc[0]  += f.x; acc[1]  += f.y;
                    f = h2f(va.y); acc[2]  += f.x; acc[3]  += f.y;
                    f = h2f(va.z); acc[4]  += f.x; acc[5]  += f.y;
                    f = h2f(va.w); acc[6]  += f.x; acc[7]  += f.y;
                    f = h2f(vb.x); acc[8]  += f.x; acc[9]  += f.y;
                    f = h2f(vb.y); acc[10] += f.x; acc[11] += f.y;
                    f = h2f(vb.z); acc[12] += f.x; acc[13] += f.y;
                    f = h2f(vb.w); acc[14] += f.x; acc[15] += f.y;

                    va = na; vb = nb;
                }
                #undef IDX_OF
            }

            {
                float* p0 = s_part + gw * DIM + 8 * lane;
                *(float4*)(p0 + 0)       = make_float4(acc[0], acc[1], acc[2], acc[3]);
                *(float4*)(p0 + 4)       = make_float4(acc[4], acc[5], acc[6], acc[7]);
                *(float4*)(p0 + 256)     = make_float4(acc[8], acc[9], acc[10], acc[11]);
                *(float4*)(p0 + 256 + 4) = make_float4(acc[12], acc[13], acc[14], acc[15]);
            }
            asm volatile("bar.sync 1, 128;" ::: "memory");

            {
                const int t   = tid - 128;      // 0..127
                const int col = t * 4;
                float s0 = 0.f, s1 = 0.f, s2 = 0.f, s3 = 0.f;
#pragma unroll
                for (int ww = 0; ww < 4; ww++) {
                    float4 p = *(const float4*)(s_part + ww * DIM + col);
                    s0 += p.x; s1 += p.y; s2 += p.z; s3 += p.w;
                }
                const float di = 1.0f / deg[row];
                uint2 yh = *(const uint2*)(g_Yh + (size_t)row * DIM + col);
                float2 y01 = h2f(yh.x);
                float2 y23 = h2f(yh.y);
                float4 bb4 = *(const float4*)(bias + col);
                float4 o;
                o.x = fmaxf(di * s0 + (1.0f + di) * y01.x + bb4.x, 0.f);
                o.y = fmaxf(di * s1 + (1.0f + di) * y01.y + bb4.y, 0.f);
                o.z = fmaxf(di * s2 + (1.0f + di) * y23.x + bb4.z, 0.f);
                o.w = fmaxf(di * s3 + (1.0f + di) * y23.y + bb4.w, 0.f);
                __stcs((float4*)(out + (size_t)row * DIM + col), o);
            }
        }
        __syncthreads();
    }
}

// ---------------------------------------------------------------------------
extern "C" void kernel_launch(void* const* d_in, const int* in_sizes, int n_in,
                              void* d_out, int out_size) {
    const float *x = nullptr, *A = nullptr, *deg = nullptr, *W = nullptr, *b = nullptr;
    for (int i = 0; i < n_in; i++) {
        long long sz = (long long)in_sizes[i];
        if      (sz == (long long)N_NODES * N_NODES) A   = (const float*)d_in[i];
        else if (sz == (long long)N_NODES * DIM)     x   = (const float*)d_in[i];
        else if (sz == (long long)DIM * DIM)         W   = (const float*)d_in[i];
        else if (sz == (long long)N_NODES)           deg = (const float*)d_in[i];
        else if (sz == (long long)DIM)               b   = (const float*)d_in[i];
    }

    cudaFuncSetAttribute(gemm_xw, cudaFuncAttributeMaxDynamicSharedMemorySize, GEMM_SMEM);

    prep_kernel<<<8448, 256>>>(x, W);
    gemm_xw<<<dim3(4, 128), 256, GEMM_SMEM>>>();
    gcn_spmm<<<SPMM_GRID, 256>>>(A, deg, b, (float*)d_out);
}

// round 16
// speedup vs baseline: 1.0068x; 1.0068x over previous
#include <cuda_runtime.h>
#include <cuda_bf16.h>
#include <cuda_fp16.h>
#include <cstdint>

#define N_NODES 16384
#define DIM 512
#define SEG_CAP 64

// Scratch: single fp16 Y used for BOTH neighbor gathers and the self term.
__device__ __half g_Yh [(size_t)N_NODES * DIM];
__device__ __half g_xh [(size_t)N_NODES * DIM];   // fp16 x
__device__ __half g_Wh [(size_t)DIM * DIM];       // fp16 W^T [n][k]

__device__ __forceinline__ float2 h2f(uint32_t r) {
    return __half22float2(*(__half2*)&r);
}
__device__ __forceinline__ uint32_t smem_u32(const void* p) {
    uint32_t a;
    asm("{ .reg .u64 t; cvta.to.shared.u64 t, %1; cvt.u32.u64 %0, t; }" : "=r"(a) : "l"(p));
    return a;
}

#define CP_ASYNC16(saddr, gptr) \
    asm volatile("cp.async.cg.shared.global [%0], [%1], 16;" :: "r"(saddr), "l"(gptr) : "memory")
#define CP_COMMIT() asm volatile("cp.async.commit_group;" ::: "memory")
#define CP_WAIT2()  asm volatile("cp.async.wait_group 2;" ::: "memory")

#define LDMX4(r0, r1, r2, r3, addr) \
    asm volatile("ldmatrix.sync.aligned.m8n8.x4.shared.b16 {%0,%1,%2,%3}, [%4];" \
                 : "=r"(r0), "=r"(r1), "=r"(r2), "=r"(r3) : "r"(addr))

// ---------------------------------------------------------------------------
// Kernel 0: merged prepass.
//   blocks [0, 4096):      g_xh = fp16(x), 8 floats/thread (2x float4)
//   blocks [4096, 4352):   g_Wh[n][k] = fp16(W[k][n])  (32x32 tile transpose)
// ---------------------------------------------------------------------------
__global__ void __launch_bounds__(256) prep_kernel(const float* __restrict__ x,
                                                   const float* __restrict__ W) {
    if (blockIdx.x < 4096) {
        const size_t i = ((size_t)blockIdx.x * 256 + threadIdx.x) * 4;
        const size_t stride = (size_t)4096 * 256 * 4;   // second half offset
#pragma unroll
        for (int h = 0; h < 2; h++) {
            const size_t idx = i + (size_t)h * stride;
            float4 v = __ldcg((const float4*)(x + idx));
            __half2 h0 = __floats2half2_rn(v.x, v.y);
            __half2 h1 = __floats2half2_rn(v.z, v.w);
            uint2 pk;
            pk.x = *(uint32_t*)&h0;
            pk.y = *(uint32_t*)&h1;
            *(uint2*)(g_xh + idx) = pk;
        }
    } else {
        __shared__ float t[32][33];
        const int b  = blockIdx.x - 4096;
        const int bx = (b & 15) * 32;   // n base
        const int by = (b >> 4) * 32;   // k base
        const int tx = threadIdx.x & 31;
        const int ty = threadIdx.x >> 5;
#pragma unroll
        for (int i = ty; i < 32; i += 8)
            t[i][tx] = W[(size_t)(by + i) * DIM + bx + tx];
        __syncthreads();
#pragma unroll
        for (int i = ty; i < 32; i += 8)
            g_Wh[(size_t)(bx + i) * DIM + by + tx] = __float2half_rn(t[tx][i]);
    }
}

// ---------------------------------------------------------------------------
// Kernel 1: Y = x @ W  (fp16 mma.sync m16n8k16 + ldmatrix + 3-stage cp.async)
// R14, byte-identical (proven).
// ---------------------------------------------------------------------------
#define STAGE_BYTES 32768
#define GEMM_SMEM   98304

__global__ void __launch_bounds__(256, 2) gemm_xw() {
    extern __shared__ char sm[];
    const uint32_t smb = smem_u32(sm);

    const int tid  = threadIdx.x;
    const int wid  = tid >> 5;
    const int lane = tid & 31;
    const int wm   = wid & 3;
    const int wn   = wid >> 2;

    const int m0 = blockIdx.y * 128;
    const int n0 = blockIdx.x * 128;

    #define PREF(t, s) do {                                                          \
        const int _kt = (t) * 64;                                                    \
        const uint32_t _ab = smb + (uint32_t)(s) * STAGE_BYTES;                      \
        const uint32_t _bb = _ab + 16384;                                            \
        _Pragma("unroll")                                                            \
        for (int _h = 0; _h < 4; _h++) {                                             \
            int _u = tid + _h * 256;                                                 \
            int _r = _u >> 3, _c = _u & 7;                                           \
            uint32_t _idx = (uint32_t)(_r * 8 + (_c ^ (_r & 7)));                    \
            CP_ASYNC16(_ab + _idx * 16, g_xh + (size_t)(m0 + _r) * DIM + _kt + _c * 8); \
            CP_ASYNC16(_bb + _idx * 16, g_Wh + (size_t)(n0 + _r) * DIM + _kt + _c * 8); \
        }                                                                            \
    } while (0)

    float c[2][8][4];
#pragma unroll
    for (int i = 0; i < 2; i++)
#pragma unroll
        for (int j = 0; j < 8; j++)
#pragma unroll
            for (int k = 0; k < 4; k++) c[i][j][k] = 0.f;

    PREF(0, 0); CP_COMMIT();
    PREF(1, 1); CP_COMMIT();
    PREF(2, 2); CP_COMMIT();

    const int a_row14 = lane & 15;
    const int a_chalf = lane >> 4;
    const int b_nrow  = (lane & 7) + ((lane >> 4) << 3);
    const int b_chalf = (lane >> 3) & 1;

#pragma unroll 1
    for (int t = 0; t < 8; t++) {
        CP_WAIT2();
        __syncthreads();
        const int s = t - (t / 3) * 3;
        const uint32_t Ab = smb + (uint32_t)s * STAGE_BYTES;
        const uint32_t Bb = Ab + 16384;

#pragma unroll
        for (int ks = 0; ks < 4; ks++) {
            uint32_t a[2][4], b[8][2];
#pragma unroll
            for (int mi = 0; mi < 2; mi++) {
                int row = wm * 32 + mi * 16 + a_row14;
                int cc  = ks * 2 + a_chalf;
                uint32_t addr = Ab + (uint32_t)(row * 8 + (cc ^ (row & 7))) * 16;
                LDMX4(a[mi][0], a[mi][1], a[mi][2], a[mi][3], addr);
            }
#pragma unroll
            for (int p = 0; p < 4; p++) {
                int n  = wn * 64 + p * 16 + b_nrow;
                int cc = ks * 2 + b_chalf;
                uint32_t addr = Bb + (uint32_t)(n * 8 + (cc ^ (n & 7))) * 16;
                LDMX4(b[2 * p][0], b[2 * p][1], b[2 * p + 1][0], b[2 * p + 1][1], addr);
            }
#pragma unroll
            for (int mi = 0; mi < 2; mi++)
#pragma unroll
                for (int ni = 0; ni < 8; ni++) {
                    asm volatile(
                        "mma.sync.aligned.m16n8k16.row.col.f32.f16.f16.f32 "
                        "{%0,%1,%2,%3}, {%4,%5,%6,%7}, {%8,%9}, {%0,%1,%2,%3};"
                        : "+f"(c[mi][ni][0]), "+f"(c[mi][ni][1]),
                          "+f"(c[mi][ni][2]), "+f"(c[mi][ni][3])
                        : "r"(a[mi][0]), "r"(a[mi][1]), "r"(a[mi][2]), "r"(a[mi][3]),
                          "r"(b[ni][0]), "r"(b[ni][1]));
                }
        }
        __syncthreads();
        if (t + 3 < 8) PREF(t + 3, s);
        CP_COMMIT();
    }

    // Epilogue: single fp16 Y store
    const int g  = lane >> 2;
    const int tg = lane & 3;
#pragma unroll
    for (int mi = 0; mi < 2; mi++) {
#pragma unroll
        for (int ni = 0; ni < 8; ni++) {
            int row0 = m0 + wm * 32 + mi * 16 + g;
            int col  = n0 + wn * 64 + ni * 8 + tg * 2;
            __half2 h01 = __floats2half2_rn(c[mi][ni][0], c[mi][ni][1]);
            __half2 h23 = __floats2half2_rn(c[mi][ni][2], c[mi][ni][3]);
            *(__half2*)(g_Yh + (size_t)row0 * DIM + col)       = h01;
            *(__half2*)(g_Yh + (size_t)(row0 + 8) * DIM + col) = h23;
        }
    }
}

// ---------------------------------------------------------------------------
// Kernel 2: fused sparse aggregation + residual + bias + relu.
// R14 version, byte-identical (measured best: ~189-192us, at its multi-
// resource equilibrium; five structural variants all landed 191+-3us).
// ---------------------------------------------------------------------------
__global__ void __launch_bounds__(256, 6) gcn_spmm(const float* __restrict__ A,
                                                   const float* __restrict__ deg,
                                                   const float* __restrict__ bias,
                                                   float* __restrict__ out) {
    __shared__ uint16_t s_idx[8 * SEG_CAP];
    __shared__ uint16_t s_all[8 * SEG_CAP];
    __shared__ int      s_cnt[8];
    __shared__ float    s_part[8 * DIM];

    const int row  = blockIdx.x;
    const int tid  = threadIdx.x;
    const int w    = tid >> 5;
    const int lane = tid & 31;
    const unsigned lml = (1u << lane) - 1u;

    // ---------------- Phase A: per-warp ballot compaction ----------------
    {
        const uint4* Ar = (const uint4*)(A + (size_t)row * N_NODES + w * 2048);
        int cnt = 0;
#pragma unroll 1
        for (int half = 0; half < 2; half++) {
            uint4 v[8];
#pragma unroll
            for (int k = 0; k < 8; k++)
                v[k] = __ldcs(Ar + (half * 8 + k) * 32 + lane);
#pragma unroll
            for (int k = 0; k < 8; k++) {
                unsigned nz  = v[k].x | v[k].y | v[k].z | v[k].w;
                unsigned any = __ballot_sync(0xFFFFFFFFu, nz != 0);
                if (any) {
                    int colbase = w * 2048 + ((half * 8 + k) * 32 + lane) * 4;
                    unsigned m;
                    m = __ballot_sync(0xFFFFFFFFu, v[k].x != 0);
                    if (v[k].x) { int p = cnt + __popc(m & lml); if (p < SEG_CAP) s_idx[w * SEG_CAP + p] = (uint16_t)(colbase + 0); }
                    cnt += __popc(m);
                    m = __ballot_sync(0xFFFFFFFFu, v[k].y != 0);
                    if (v[k].y) { int p = cnt + __popc(m & lml); if (p < SEG_CAP) s_idx[w * SEG_CAP + p] = (uint16_t)(colbase + 1); }
                    cnt += __popc(m);
                    m = __ballot_sync(0xFFFFFFFFu, v[k].z != 0);
                    if (v[k].z) { int p = cnt + __popc(m & lml); if (p < SEG_CAP) s_idx[w * SEG_CAP + p] = (uint16_t)(colbase + 2); }
                    cnt += __popc(m);
                    m = __ballot_sync(0xFFFFFFFFu, v[k].w != 0);
                    if (v[k].w) { int p = cnt + __popc(m & lml); if (p < SEG_CAP) s_idx[w * SEG_CAP + p] = (uint16_t)(colbase + 3); }
                    cnt += __popc(m);
                }
            }
        }
        if (lane == 0) s_cnt[w] = (cnt < SEG_CAP) ? cnt : SEG_CAP;
    }
    __syncthreads();

    // ---------------- Concatenate lists (balanced gather setup) ----------------
    int tot = 0;
    {
        int off = 0;
#pragma unroll
        for (int ww = 0; ww < 8; ww++) {
            int c = s_cnt[ww];
            if (ww < w) off += c;
            tot += c;
        }
        const int mycnt = s_cnt[w];
        for (int i = lane; i < mycnt; i += 32)
            s_all[off + i] = s_idx[w * SEG_CAP + i];
    }
    __syncthreads();

    // ---------------- Phase B: balanced depth-1 pipelined gather ----------------
    float acc[16];
#pragma unroll
    for (int i = 0; i < 16; i++) acc[i] = 0.f;

    if (w < tot) {
        int g = w;
        int j = s_all[g];
        const uint4* yp = (const uint4*)(g_Yh + (size_t)j * DIM);
        uint4 va = yp[lane];
        uint4 vb = yp[32 + lane];
#pragma unroll 1
        for (; g < tot; g += 8) {
            int gn = (g + 8 < tot) ? (g + 8) : g;
            int jn = s_all[gn];
            const uint4* ypn = (const uint4*)(g_Yh + (size_t)jn * DIM);
            uint4 na = ypn[lane];
            uint4 nb = ypn[32 + lane];

            float2 f;
            f = h2f(va.x); acc[0]  += f.x; acc[1]  += f.y;
            f = h2f(va.y); acc[2]  += f.x; acc[3]  += f.y;
            f = h2f(va.z); acc[4]  += f.x; acc[5]  += f.y;
            f = h2f(va.w); acc[6]  += f.x; acc[7]  += f.y;
            f = h2f(vb.x); acc[8]  += f.x; acc[9]  += f.y;
            f = h2f(vb.y); acc[10] += f.x; acc[11] += f.y;
            f = h2f(vb.z); acc[12] += f.x; acc[13] += f.y;
            f = h2f(vb.w); acc[14] += f.x; acc[15] += f.y;

            va = na; vb = nb;
        }
    }

    {
        float* p0 = s_part + w * DIM + 8 * lane;
        *(float4*)(p0 + 0)       = make_float4(acc[0], acc[1], acc[2], acc[3]);
        *(float4*)(p0 + 4)       = make_float4(acc[4], acc[5], acc[6], acc[7]);
        *(float4*)(p0 + 256)     = make_float4(acc[8], acc[9], acc[10], acc[11]);
        *(float4*)(p0 + 256 + 4) = make_float4(acc[12], acc[13], acc[14], acc[15]);
    }
    __syncthreads();

    {
        const int col = tid * 2;
        float a0 = 0.f, a1 = 0.f;
#pragma unroll
        for (int ww = 0; ww < 8; ww++) {
            float2 p = *(const float2*)(s_part + ww * DIM + col);
            a0 += p.x; a1 += p.y;
        }
        const float di = 1.0f / deg[row];
        float2 ys = __half22float2(*(const __half2*)(g_Yh + (size_t)row * DIM + col));
        float2 bb = *(const float2*)(bias + col);
        float o0 = fmaxf(di * a0 + (1.0f + di) * ys.x + bb.x, 0.f);
        float o1 = fmaxf(di * a1 + (1.0f + di) * ys.y + bb.y, 0.f);
        *(float2*)(out + (size_t)row * DIM + col) = make_float2(o0, o1);
    }
}

// ---------------------------------------------------------------------------
extern "C" void kernel_launch(void* const* d_in, const int* in_sizes, int n_in,
                              void* d_out, int out_size) {
    const float *x = nullptr, *A = nullptr, *deg = nullptr, *W = nullptr, *b = nullptr;
    for (int i = 0; i < n_in; i++) {
        long long sz = (long long)in_sizes[i];
        if      (sz == (long long)N_NODES * N_NODES) A   = (const float*)d_in[i];
        else if (sz == (long long)N_NODES * DIM)     x   = (const float*)d_in[i];
        else if (sz == (long long)DIM * DIM)         W   = (const float*)d_in[i];
        else if (sz == (long long)N_NODES)           deg = (const float*)d_in[i];
        else if (sz == (long long)DIM)               b   = (const float*)d_in[i];
    }

    cudaFuncSetAttribute(gemm_xw, cudaFuncAttributeMaxDynamicSharedMemorySize, GEMM_SMEM);

    prep_kernel<<<4352, 256>>>(x, W);
    gemm_xw<<<dim3(4, 128), 256, GEMM_SMEM>>>();
    gcn_spmm<<<N_NODES, 256>>>(A, deg, b, (float*)d_out);
}